// round 4
// baseline (speedup 1.0000x reference)
#include <cuda_runtime.h>
#include <cuda_fp16.h>
#include <cstdint>

#define N_TOK   8192
#define D_MODEL 1024
#define D_DICT  16384
#define TOPK    32

__device__ __half g_xh[(size_t)N_TOK * D_MODEL];
__device__ __half g_xl[(size_t)N_TOK * D_MODEL];
__device__ __half g_wh[(size_t)D_DICT * D_MODEL];
__device__ __half g_wl[(size_t)D_DICT * D_MODEL];
__device__ float  g_wdecT[(size_t)D_DICT * D_MODEL];
__device__ int    g_selIdx[(size_t)N_TOK * TOPK];
__device__ float  g_selVal[(size_t)N_TOK * TOPK];

__device__ __forceinline__ unsigned long long umax64(unsigned long long a, unsigned long long b) {
    return a > b ? a : b;
}
__device__ __forceinline__ void cp16(void* dst, const void* src) {
    unsigned sd = (unsigned)__cvta_generic_to_shared(dst);
    asm volatile("cp.async.cg.shared.global [%0], [%1], 16;\n" :: "r"(sd), "l"(src));
}
__device__ __forceinline__ void ldsm4(uint32_t* r, const void* p) {
    unsigned a = (unsigned)__cvta_generic_to_shared(p);
    asm volatile("ldmatrix.sync.aligned.m8n8.x4.shared.b16 {%0,%1,%2,%3}, [%4];\n"
                 : "=r"(r[0]), "=r"(r[1]), "=r"(r[2]), "=r"(r[3]) : "r"(a));
}
__device__ __forceinline__ void mma16816(float* c, const uint32_t* a, uint32_t b0, uint32_t b1) {
    asm volatile(
        "mma.sync.aligned.m16n8k16.row.col.f32.f16.f16.f32 "
        "{%0,%1,%2,%3}, {%4,%5,%6,%7}, {%8,%9}, {%0,%1,%2,%3};\n"
        : "+f"(c[0]), "+f"(c[1]), "+f"(c[2]), "+f"(c[3])
        : "r"(a[0]), "r"(a[1]), "r"(a[2]), "r"(a[3]), "r"(b0), "r"(b1));
}

// ---- split fp32 -> (hi, lo) fp16 ----
__device__ __forceinline__ void split4(const float4 v, __half2* hp, __half2* lp, size_t i2) {
    __half h0 = __float2half(v.x), h1 = __float2half(v.y);
    __half h2 = __float2half(v.z), h3 = __float2half(v.w);
    hp[i2]     = __halves2half2(h0, h1);
    hp[i2 + 1] = __halves2half2(h2, h3);
    lp[i2]     = __halves2half2(__float2half(v.x - __half2float(h0)),
                                __float2half(v.y - __half2float(h1)));
    lp[i2 + 1] = __halves2half2(__float2half(v.z - __half2float(h2)),
                                __float2half(v.w - __half2float(h3)));
}
__global__ void split_x_kernel(const float4* __restrict__ src) {
    size_t i = (size_t)blockIdx.x * 256 + threadIdx.x;
    split4(src[i], (__half2*)g_xh, (__half2*)g_xl, i * 2);
}
__global__ void split_w_kernel(const float4* __restrict__ src) {
    size_t i = (size_t)blockIdx.x * 256 + threadIdx.x;
    split4(src[i], (__half2*)g_wh, (__half2*)g_wl, i * 2);
}

// ---- transpose W_dec ----
__global__ void transpose_wdec_kernel(const float* __restrict__ wdec) {
    __shared__ float t[32][33];
    int fx = blockIdx.x * 32 + threadIdx.x;
    int dy = blockIdx.y * 32 + threadIdx.y;
#pragma unroll
    for (int j = 0; j < 32; j += 8)
        t[threadIdx.y + j][threadIdx.x] = wdec[(size_t)(dy + j) * D_DICT + fx];
    __syncthreads();
    int dx = blockIdx.y * 32 + threadIdx.x;
    int fy = blockIdx.x * 32 + threadIdx.y;
#pragma unroll
    for (int j = 0; j < 32; j += 8)
        g_wdecT[(size_t)(fy + j) * D_MODEL + dx] = t[threadIdx.x][threadIdx.y + j];
}

// ---- encoder GEMM: fp16x3 (xh*wh + xh*wl + xl*wh), fp32 accum ----
// 128x256 CTA tile, 8 warps (2x4), 64x64 warp tile, BK=32, 4-stage cp.async pipe.
#define BM 128
#define BN 256
#define BK 32
#define ASTRIDE 40
#define NSTG 4
#define NCHUNK (3 * (D_MODEL / BK))   // 96
#define STG_A_HALFS (BM * ASTRIDE)    // 5120 halfs
#define STG_B_HALFS (BN * ASTRIDE)    // 10240 halfs
#define STG_HALFS   (STG_A_HALFS + STG_B_HALFS)
#define ENC_SMEM (NSTG * STG_HALFS * 2)   // 122880 B

__global__ __launch_bounds__(256, 1) void enc_gemm_kernel(const float* __restrict__ b_enc,
                                                          float* __restrict__ zout) {
    extern __shared__ __half sh[];
    const int tid  = threadIdx.x;
    const int lane = tid & 31;
    const int wid  = tid >> 5;
    const int wm   = wid & 1;    // 2 warps along M
    const int wn   = wid >> 1;   // 4 warps along N
    const int mBase = blockIdx.y * BM;
    const int nBase = blockIdx.x * BN;

    float acc[4][8][4];
#pragma unroll
    for (int a = 0; a < 4; a++)
#pragma unroll
        for (int b = 0; b < 8; b++)
#pragma unroll
            for (int c = 0; c < 4; c++) acc[a][b][c] = 0.f;

    auto loadChunk = [&](int s) {
        const int pass = s >> 5;                 // 0:xh*wh 1:xh*wl 2:xl*wh
        const int k0   = (s & 31) * BK;
        const __half* Ap = (pass == 2) ? g_xl : g_xh;
        const __half* Bp = (pass == 1) ? g_wl : g_wh;
        __half* sA = sh + (s & (NSTG - 1)) * STG_HALFS;
        __half* sB = sA + STG_A_HALFS;
#pragma unroll
        for (int i = 0; i < 2; i++) {            // A: 512 cp16
            int idx = tid + i * 256;
            int row = idx >> 2, c = (idx & 3) * 8;
            cp16(sA + row * ASTRIDE + c, Ap + (size_t)(mBase + row) * D_MODEL + k0 + c);
        }
#pragma unroll
        for (int i = 0; i < 4; i++) {            // B: 1024 cp16
            int idx = tid + i * 256;
            int row = idx >> 2, c = (idx & 3) * 8;
            cp16(sB + row * ASTRIDE + c, Bp + (size_t)(nBase + row) * D_MODEL + k0 + c);
        }
        asm volatile("cp.async.commit_group;\n");
    };

    auto compute = [&](int s) {
        const __half* sA = sh + (s & (NSTG - 1)) * STG_HALFS;
        const __half* sB = sA + STG_A_HALFS;
#pragma unroll
        for (int ks = 0; ks < 2; ks++) {
            uint32_t a[4][4], b[4][4];
            const int arow = wm * 64 + (lane & 15);
            const int acol = ks * 16 + ((lane >> 4) << 3);
#pragma unroll
            for (int mt = 0; mt < 4; mt++)
                ldsm4(a[mt], sA + (arow + mt * 16) * ASTRIDE + acol);
            const int brow = wn * 64 + (lane & 7) + ((lane >> 4) << 3);
            const int bcol = ks * 16 + (((lane >> 3) & 1) << 3);
#pragma unroll
            for (int nt2 = 0; nt2 < 4; nt2++)
                ldsm4(b[nt2], sB + (brow + nt2 * 16) * ASTRIDE + bcol);
#pragma unroll
            for (int mt = 0; mt < 4; mt++)
#pragma unroll
                for (int nt = 0; nt < 8; nt++) {
                    const uint32_t* bb = &b[nt >> 1][(nt & 1) * 2];
                    mma16816(acc[mt][nt], a[mt], bb[0], bb[1]);
                }
        }
    };

    loadChunk(0);
    loadChunk(1);
    loadChunk(2);
    for (int s = 0; s < NCHUNK; s++) {
        asm volatile("cp.async.wait_group 2;\n");
        __syncthreads();
        if (s + 3 < NCHUNK) loadChunk(s + 3);
        else                asm volatile("cp.async.commit_group;\n");
        compute(s);
    }

    // epilogue: + bias, write z
    const int r0 = mBase + wm * 64 + (lane >> 2);
#pragma unroll
    for (int nt = 0; nt < 8; nt++) {
        const int c = nBase + wn * 64 + nt * 8 + 2 * (lane & 3);
        const float b0 = __ldg(&b_enc[c]);
        const float b1 = __ldg(&b_enc[c + 1]);
#pragma unroll
        for (int mt = 0; mt < 4; mt++) {
            const int r = r0 + mt * 16;
            float2 v0 = make_float2(acc[mt][nt][0] + b0, acc[mt][nt][1] + b1);
            float2 v1 = make_float2(acc[mt][nt][2] + b0, acc[mt][nt][3] + b1);
            *(float2*)(zout + (size_t)r * D_DICT + c)       = v0;
            *(float2*)(zout + (size_t)(r + 8) * D_DICT + c) = v1;
        }
    }
}

// ---- per-row exact top-32 by |z|; sparsify z in place ----
__global__ __launch_bounds__(256) void topk_kernel(float* __restrict__ z) {
    __shared__ uint32_t whist[8][1024];
    __shared__ uint2    cand[1024];
    __shared__ uint32_t sums[256];
    __shared__ unsigned long long red[8];
    __shared__ unsigned long long winner;
    __shared__ uint32_t ncand_s, binB_s;

    const int tid  = threadIdx.x;
    const int lane = tid & 31;
    const int wid  = tid >> 5;
    const int row  = blockIdx.x;
    float* zr = z + (size_t)row * D_DICT;

    for (int i = tid; i < 8 * 1024; i += 256) ((uint32_t*)whist)[i] = 0;
    if (tid == 0) ncand_s = 0;
    __syncthreads();

    for (int i = tid; i < D_DICT; i += 256) {
        uint32_t key = __float_as_uint(zr[i]) & 0x7FFFFFFFu;
        atomicAdd(&whist[wid][key >> 21], 1u);
    }
    __syncthreads();

    for (int b = tid; b < 1024; b += 256) {
        uint32_t t = 0;
#pragma unroll
        for (int w = 0; w < 8; w++) t += whist[w][b];
        whist[0][b] = t;
    }
    __syncthreads();

    {
        uint32_t s = 0;
#pragma unroll
        for (int j = 0; j < 4; j++) s += whist[0][tid * 4 + j];
        sums[tid] = s;
        __syncthreads();
        for (int off = 1; off < 256; off <<= 1) {
            uint32_t v = sums[tid] + ((tid + off < 256) ? sums[tid + off] : 0u);
            __syncthreads();
            sums[tid] = v;
            __syncthreads();
        }
    }
    if (sums[tid] >= TOPK && (tid == 255 || sums[tid + 1] < TOPK)) {
        uint32_t acc = (tid == 255) ? 0u : sums[tid + 1];
        int B = tid * 4;
        for (int b = tid * 4 + 3; b >= tid * 4; b--) {
            acc += whist[0][b];
            if (acc >= TOPK) { B = b; break; }
        }
        binB_s = (uint32_t)B;
    }
    __syncthreads();
    const uint32_t keymin = binB_s << 21;

    for (int i = tid; i < D_DICT; i += 256) {
        uint32_t bits = __float_as_uint(zr[i]);
        uint32_t key  = bits & 0x7FFFFFFFu;
        if (key >= keymin) {
            uint32_t p = atomicAdd(&ncand_s, 1u);
            if (p < 1024) cand[p] = make_uint2(bits, (uint32_t)i);
            else          zr[i] = 0.0f;
        } else {
            zr[i] = 0.0f;
        }
    }
    __syncthreads();
    const uint32_t nc = min(ncand_s, 1024u);

    unsigned long long pk[4];
#pragma unroll
    for (int j = 0; j < 4; j++) {
        int p = tid + j * 256;
        pk[j] = 0ull;
        if (p < (int)nc) {
            uint32_t key = cand[p].x & 0x7FFFFFFFu;
            pk[j] = ((unsigned long long)key << 32) |
                    (unsigned long long)(0xFFFFFFFFu - cand[p].y);
        }
    }

    for (int it = 0; it < TOPK; it++) {
        unsigned long long v = umax64(umax64(pk[0], pk[1]), umax64(pk[2], pk[3]));
#pragma unroll
        for (int off = 16; off; off >>= 1)
            v = umax64(v, __shfl_xor_sync(0xFFFFFFFFu, v, off));
        if (lane == 0) red[wid] = v;
        __syncthreads();
        if (tid == 0) {
            unsigned long long w = red[0];
#pragma unroll
            for (int k = 1; k < 8; k++) w = umax64(w, red[k]);
            winner = w;
        }
        __syncthreads();
        const unsigned long long w = winner;
#pragma unroll
        for (int j = 0; j < 4; j++) {
            if (w != 0ull && pk[j] == w) {
                uint32_t idx = 0xFFFFFFFFu - (uint32_t)w;
                g_selIdx[(size_t)row * TOPK + it] = (int)idx;
                g_selVal[(size_t)row * TOPK + it] = __uint_as_float(cand[tid + j * 256].x);
                pk[j] = 0ull;
            }
        }
        __syncthreads();
    }

#pragma unroll
    for (int j = 0; j < 4; j++) {
        if (pk[j] != 0ull) {
            uint32_t idx = 0xFFFFFFFFu - (uint32_t)pk[j];
            zr[idx] = 0.0f;
        }
    }
}

// ---- sparse decoder ----
__global__ __launch_bounds__(256) void decode_kernel(const float* __restrict__ b_dec,
                                                     float* __restrict__ recon) {
    const int row = blockIdx.x;
    const int tid = threadIdx.x;
    __shared__ int   sIdx[TOPK];
    __shared__ float sVal[TOPK];
    if (tid < TOPK) {
        sIdx[tid] = g_selIdx[(size_t)row * TOPK + tid];
        sVal[tid] = g_selVal[(size_t)row * TOPK + tid];
    }
    __syncthreads();
    const int d0 = tid * 4;
    float4 acc = *(const float4*)(b_dec + d0);
#pragma unroll 8
    for (int j = 0; j < TOPK; j++) {
        const float v = sVal[j];
        const float4 w = *(const float4*)(g_wdecT + (size_t)sIdx[j] * D_MODEL + d0);
        acc.x += v * w.x; acc.y += v * w.y; acc.z += v * w.z; acc.w += v * w.w;
    }
    *(float4*)(recon + (size_t)row * D_MODEL + d0) = acc;
}

extern "C" void kernel_launch(void* const* d_in, const int* in_sizes, int n_in,
                              void* d_out, int out_size) {
    const float* x    = (const float*)d_in[0];
    const float* Wenc = (const float*)d_in[1];
    const float* benc = (const float*)d_in[2];
    const float* Wdec = (const float*)d_in[3];
    const float* bdec = (const float*)d_in[4];
    float* recon = (float*)d_out;
    float* z     = recon + (size_t)N_TOK * D_MODEL;

    static int attr_set = 0;
    if (!attr_set) {
        cudaFuncSetAttribute(enc_gemm_kernel, cudaFuncAttributeMaxDynamicSharedMemorySize,
                             ENC_SMEM);
        attr_set = 1;
    }

    split_x_kernel<<<N_TOK * D_MODEL / 4 / 256, 256>>>((const float4*)x);
    split_w_kernel<<<D_DICT * D_MODEL / 4 / 256, 256>>>((const float4*)Wenc);
    transpose_wdec_kernel<<<dim3(D_DICT / 32, D_MODEL / 32), dim3(32, 8)>>>(Wdec);
    enc_gemm_kernel<<<dim3(D_DICT / BN, N_TOK / BM), 256, ENC_SMEM>>>(benc, z);
    topk_kernel<<<N_TOK, 256>>>(z);
    decode_kernel<<<N_TOK, 256>>>(bdec, recon);
}

// round 5
// speedup vs baseline: 1.2129x; 1.2129x over previous
#include <cuda_runtime.h>
#include <cuda_fp16.h>
#include <cstdint>

#define N_TOK   8192
#define D_MODEL 1024
#define D_DICT  16384
#define TOPK    32

__device__ __half g_xh[(size_t)N_TOK * D_MODEL];
__device__ __half g_xl[(size_t)N_TOK * D_MODEL];
__device__ __half g_wh[(size_t)D_DICT * D_MODEL];
__device__ __half g_wl[(size_t)D_DICT * D_MODEL];
__device__ float  g_wdecT[(size_t)D_DICT * D_MODEL];
__device__ int    g_selIdx[(size_t)N_TOK * TOPK];
__device__ float  g_selVal[(size_t)N_TOK * TOPK];

__device__ __forceinline__ unsigned long long umax64(unsigned long long a, unsigned long long b) {
    return a > b ? a : b;
}
__device__ __forceinline__ void cp16(void* dst, const void* src) {
    unsigned sd = (unsigned)__cvta_generic_to_shared(dst);
    asm volatile("cp.async.cg.shared.global [%0], [%1], 16;\n" :: "r"(sd), "l"(src));
}
__device__ __forceinline__ void ldsm4(uint32_t* r, const void* p) {
    unsigned a = (unsigned)__cvta_generic_to_shared(p);
    asm volatile("ldmatrix.sync.aligned.m8n8.x4.shared.b16 {%0,%1,%2,%3}, [%4];\n"
                 : "=r"(r[0]), "=r"(r[1]), "=r"(r[2]), "=r"(r[3]) : "r"(a));
}
__device__ __forceinline__ void mma16816(float* c, const uint32_t* a, uint32_t b0, uint32_t b1) {
    asm volatile(
        "mma.sync.aligned.m16n8k16.row.col.f32.f16.f16.f32 "
        "{%0,%1,%2,%3}, {%4,%5,%6,%7}, {%8,%9}, {%0,%1,%2,%3};\n"
        : "+f"(c[0]), "+f"(c[1]), "+f"(c[2]), "+f"(c[3])
        : "r"(a[0]), "r"(a[1]), "r"(a[2]), "r"(a[3]), "r"(b0), "r"(b1));
}

// ---- split fp32 -> (hi, lo) fp16 ----
__device__ __forceinline__ void split4(const float4 v, __half2* hp, __half2* lp, size_t i2) {
    __half h0 = __float2half(v.x), h1 = __float2half(v.y);
    __half h2 = __float2half(v.z), h3 = __float2half(v.w);
    hp[i2]     = __halves2half2(h0, h1);
    hp[i2 + 1] = __halves2half2(h2, h3);
    lp[i2]     = __halves2half2(__float2half(v.x - __half2float(h0)),
                                __float2half(v.y - __half2float(h1)));
    lp[i2 + 1] = __halves2half2(__float2half(v.z - __half2float(h2)),
                                __float2half(v.w - __half2float(h3)));
}
__global__ void split_x_kernel(const float4* __restrict__ src) {
    size_t i = (size_t)blockIdx.x * 256 + threadIdx.x;
    split4(src[i], (__half2*)g_xh, (__half2*)g_xl, i * 2);
}
__global__ void split_w_kernel(const float4* __restrict__ src) {
    size_t i = (size_t)blockIdx.x * 256 + threadIdx.x;
    split4(src[i], (__half2*)g_wh, (__half2*)g_wl, i * 2);
}

// ---- transpose W_dec ----
__global__ void transpose_wdec_kernel(const float* __restrict__ wdec) {
    __shared__ float t[32][33];
    int fx = blockIdx.x * 32 + threadIdx.x;
    int dy = blockIdx.y * 32 + threadIdx.y;
#pragma unroll
    for (int j = 0; j < 32; j += 8)
        t[threadIdx.y + j][threadIdx.x] = wdec[(size_t)(dy + j) * D_DICT + fx];
    __syncthreads();
    int dx = blockIdx.y * 32 + threadIdx.x;
    int fy = blockIdx.x * 32 + threadIdx.y;
#pragma unroll
    for (int j = 0; j < 32; j += 8)
        g_wdecT[(size_t)(fy + j) * D_MODEL + dx] = t[threadIdx.x][threadIdx.y + j];
}

// ---- encoder GEMM: fp16x3 (xh*wh + xh*wl + xl*wh), fp32 accum ----
// 128x128 CTA tile, 8 warps (4x2), 32x64 warp tile, BK=32, 4-stage pipe, 2 CTA/SM.
#define BM 128
#define BN 128
#define BK 32
#define ASTRIDE 40
#define NSTG 4
#define NCHUNK (3 * (D_MODEL / BK))   // 96
#define STG_A_HALFS (BM * ASTRIDE)
#define STG_B_HALFS (BN * ASTRIDE)
#define STG_HALFS   (STG_A_HALFS + STG_B_HALFS)
#define ENC_SMEM (NSTG * STG_HALFS * 2)   // 81920 B

__global__ __launch_bounds__(256, 2) void enc_gemm_kernel(const float* __restrict__ b_enc,
                                                          float* __restrict__ zout) {
    extern __shared__ __half sh[];
    const int tid  = threadIdx.x;
    const int lane = tid & 31;
    const int wid  = tid >> 5;
    const int wm   = wid & 3;    // 4 warps along M
    const int wn   = wid >> 2;   // 2 warps along N
    const int mBase = blockIdx.y * BM;
    const int nBase = blockIdx.x * BN;

    float acc[2][8][4];
#pragma unroll
    for (int a = 0; a < 2; a++)
#pragma unroll
        for (int b = 0; b < 8; b++)
#pragma unroll
            for (int c = 0; c < 4; c++) acc[a][b][c] = 0.f;

    auto loadChunk = [&](int s) {
        const int pass = s >> 5;                 // 0:xh*wh 1:xh*wl 2:xl*wh
        const int k0   = (s & 31) * BK;
        const __half* Ap = (pass == 2) ? g_xl : g_xh;
        const __half* Bp = (pass == 1) ? g_wl : g_wh;
        __half* sA = sh + (s & (NSTG - 1)) * STG_HALFS;
        __half* sB = sA + STG_A_HALFS;
#pragma unroll
        for (int i = 0; i < 2; i++) {
            int idx = tid + i * 256;
            int row = idx >> 2, c = (idx & 3) * 8;
            cp16(sA + row * ASTRIDE + c, Ap + (size_t)(mBase + row) * D_MODEL + k0 + c);
            cp16(sB + row * ASTRIDE + c, Bp + (size_t)(nBase + row) * D_MODEL + k0 + c);
        }
        asm volatile("cp.async.commit_group;\n");
    };

    auto compute = [&](int s) {
        const __half* sA = sh + (s & (NSTG - 1)) * STG_HALFS;
        const __half* sB = sA + STG_A_HALFS;
#pragma unroll
        for (int ks = 0; ks < 2; ks++) {
            uint32_t a[2][4], b[4][4];
            const int arow = wm * 32 + (lane & 15);
            const int acol = ks * 16 + ((lane >> 4) << 3);
#pragma unroll
            for (int mt = 0; mt < 2; mt++)
                ldsm4(a[mt], sA + (arow + mt * 16) * ASTRIDE + acol);
            const int brow = wn * 64 + (lane & 7) + ((lane >> 4) << 3);
            const int bcol = ks * 16 + (((lane >> 3) & 1) << 3);
#pragma unroll
            for (int nt2 = 0; nt2 < 4; nt2++)
                ldsm4(b[nt2], sB + (brow + nt2 * 16) * ASTRIDE + bcol);
#pragma unroll
            for (int mt = 0; mt < 2; mt++)
#pragma unroll
                for (int nt = 0; nt < 8; nt++) {
                    const uint32_t* bb = &b[nt >> 1][(nt & 1) * 2];
                    mma16816(acc[mt][nt], a[mt], bb[0], bb[1]);
                }
        }
    };

    loadChunk(0);
    loadChunk(1);
    loadChunk(2);
    for (int s = 0; s < NCHUNK; s++) {
        asm volatile("cp.async.wait_group 2;\n");
        __syncthreads();
        if (s + 3 < NCHUNK) loadChunk(s + 3);
        else                asm volatile("cp.async.commit_group;\n");
        compute(s);
    }

    // epilogue: + bias, write z
    const int r0 = mBase + wm * 32 + (lane >> 2);
#pragma unroll
    for (int nt = 0; nt < 8; nt++) {
        const int c = nBase + wn * 64 + nt * 8 + 2 * (lane & 3);
        const float b0 = __ldg(&b_enc[c]);
        const float b1 = __ldg(&b_enc[c + 1]);
#pragma unroll
        for (int mt = 0; mt < 2; mt++) {
            const int r = r0 + mt * 16;
            float2 v0 = make_float2(acc[mt][nt][0] + b0, acc[mt][nt][1] + b1);
            float2 v1 = make_float2(acc[mt][nt][2] + b0, acc[mt][nt][3] + b1);
            *(float2*)(zout + (size_t)r * D_DICT + c)       = v0;
            *(float2*)(zout + (size_t)(r + 8) * D_DICT + c) = v1;
        }
    }
}

// ---- per-row exact top-32 by |z|; sparsify z in place ----
__global__ __launch_bounds__(256) void topk_kernel(float* __restrict__ z) {
    __shared__ uint32_t whist[8][1024];
    __shared__ uint2    cand[1024];
    __shared__ uint32_t sums[256];
    __shared__ unsigned long long red[8];
    __shared__ unsigned long long winner;
    __shared__ uint32_t ncand_s, binB_s;

    const int tid  = threadIdx.x;
    const int lane = tid & 31;
    const int wid  = tid >> 5;
    const int row  = blockIdx.x;
    float* zr = z + (size_t)row * D_DICT;

    for (int i = tid; i < 8 * 1024; i += 256) ((uint32_t*)whist)[i] = 0;
    if (tid == 0) ncand_s = 0;
    __syncthreads();

    for (int i = tid; i < D_DICT; i += 256) {
        uint32_t key = __float_as_uint(zr[i]) & 0x7FFFFFFFu;
        atomicAdd(&whist[wid][key >> 21], 1u);
    }
    __syncthreads();

    for (int b = tid; b < 1024; b += 256) {
        uint32_t t = 0;
#pragma unroll
        for (int w = 0; w < 8; w++) t += whist[w][b];
        whist[0][b] = t;
    }
    __syncthreads();

    {
        uint32_t s = 0;
#pragma unroll
        for (int j = 0; j < 4; j++) s += whist[0][tid * 4 + j];
        sums[tid] = s;
        __syncthreads();
        for (int off = 1; off < 256; off <<= 1) {
            uint32_t v = sums[tid] + ((tid + off < 256) ? sums[tid + off] : 0u);
            __syncthreads();
            sums[tid] = v;
            __syncthreads();
        }
    }
    if (sums[tid] >= TOPK && (tid == 255 || sums[tid + 1] < TOPK)) {
        uint32_t acc = (tid == 255) ? 0u : sums[tid + 1];
        int B = tid * 4;
        for (int b = tid * 4 + 3; b >= tid * 4; b--) {
            acc += whist[0][b];
            if (acc >= TOPK) { B = b; break; }
        }
        binB_s = (uint32_t)B;
    }
    __syncthreads();
    const uint32_t keymin = binB_s << 21;

    for (int i = tid; i < D_DICT; i += 256) {
        uint32_t bits = __float_as_uint(zr[i]);
        uint32_t key  = bits & 0x7FFFFFFFu;
        if (key >= keymin) {
            uint32_t p = atomicAdd(&ncand_s, 1u);
            if (p < 1024) cand[p] = make_uint2(bits, (uint32_t)i);
            else          zr[i] = 0.0f;
        } else {
            zr[i] = 0.0f;
        }
    }
    __syncthreads();
    const uint32_t nc = min(ncand_s, 1024u);

    unsigned long long pk[4];
#pragma unroll
    for (int j = 0; j < 4; j++) {
        int p = tid + j * 256;
        pk[j] = 0ull;
        if (p < (int)nc) {
            uint32_t key = cand[p].x & 0x7FFFFFFFu;
            pk[j] = ((unsigned long long)key << 32) |
                    (unsigned long long)(0xFFFFFFFFu - cand[p].y);
        }
    }

    for (int it = 0; it < TOPK; it++) {
        unsigned long long v = umax64(umax64(pk[0], pk[1]), umax64(pk[2], pk[3]));
#pragma unroll
        for (int off = 16; off; off >>= 1)
            v = umax64(v, __shfl_xor_sync(0xFFFFFFFFu, v, off));
        if (lane == 0) red[wid] = v;
        __syncthreads();
        if (tid == 0) {
            unsigned long long w = red[0];
#pragma unroll
            for (int k = 1; k < 8; k++) w = umax64(w, red[k]);
            winner = w;
        }
        __syncthreads();
        const unsigned long long w = winner;
#pragma unroll
        for (int j = 0; j < 4; j++) {
            if (w != 0ull && pk[j] == w) {
                uint32_t idx = 0xFFFFFFFFu - (uint32_t)w;
                g_selIdx[(size_t)row * TOPK + it] = (int)idx;
                g_selVal[(size_t)row * TOPK + it] = __uint_as_float(cand[tid + j * 256].x);
                pk[j] = 0ull;
            }
        }
        __syncthreads();
    }

#pragma unroll
    for (int j = 0; j < 4; j++) {
        if (pk[j] != 0ull) {
            uint32_t idx = 0xFFFFFFFFu - (uint32_t)pk[j];
            zr[idx] = 0.0f;
        }
    }
}

// ---- sparse decoder ----
__global__ __launch_bounds__(256) void decode_kernel(const float* __restrict__ b_dec,
                                                     float* __restrict__ recon) {
    const int row = blockIdx.x;
    const int tid = threadIdx.x;
    __shared__ int   sIdx[TOPK];
    __shared__ float sVal[TOPK];
    if (tid < TOPK) {
        sIdx[tid] = g_selIdx[(size_t)row * TOPK + tid];
        sVal[tid] = g_selVal[(size_t)row * TOPK + tid];
    }
    __syncthreads();
    const int d0 = tid * 4;
    float4 acc = *(const float4*)(b_dec + d0);
#pragma unroll 8
    for (int j = 0; j < TOPK; j++) {
        const float v = sVal[j];
        const float4 w = *(const float4*)(g_wdecT + (size_t)sIdx[j] * D_MODEL + d0);
        acc.x += v * w.x; acc.y += v * w.y; acc.z += v * w.z; acc.w += v * w.w;
    }
    *(float4*)(recon + (size_t)row * D_MODEL + d0) = acc;
}

extern "C" void kernel_launch(void* const* d_in, const int* in_sizes, int n_in,
                              void* d_out, int out_size) {
    const float* x    = (const float*)d_in[0];
    const float* Wenc = (const float*)d_in[1];
    const float* benc = (const float*)d_in[2];
    const float* Wdec = (const float*)d_in[3];
    const float* bdec = (const float*)d_in[4];
    float* recon = (float*)d_out;
    float* z     = recon + (size_t)N_TOK * D_MODEL;

    static int attr_set = 0;
    if (!attr_set) {
        cudaFuncSetAttribute(enc_gemm_kernel, cudaFuncAttributeMaxDynamicSharedMemorySize,
                             ENC_SMEM);
        attr_set = 1;
    }

    split_x_kernel<<<N_TOK * D_MODEL / 4 / 256, 256>>>((const float4*)x);
    split_w_kernel<<<D_DICT * D_MODEL / 4 / 256, 256>>>((const float4*)Wenc);
    transpose_wdec_kernel<<<dim3(D_DICT / 32, D_MODEL / 32), dim3(32, 8)>>>(Wdec);
    enc_gemm_kernel<<<dim3(D_DICT / BN, N_TOK / BM), 256, ENC_SMEM>>>(benc, z);
    topk_kernel<<<N_TOK, 256>>>(z);
    decode_kernel<<<N_TOK, 256>>>(bdec, recon);
}